// round 10
// baseline (speedup 1.0000x reference)
#include <cuda_runtime.h>
#include <cstdint>

#define NN 100000
#define NE 800000
#define HID 256
#define BN 32

typedef unsigned long long u64;

// Scratch (allocation-free rule: __device__ globals). 16B-aligned for float4 access.
__device__ __align__(16) float g_dinv[NN];
__device__ __align__(16) float g_hs[NN * BN];     // row-prescaled features
__device__ __align__(16) float g_agg[NN * BN];    // aggregation accumulator

// ---- f32x2 packed helpers -------------------------------------------------
__device__ __forceinline__ u64 pk2(float lo, float hi) {
    u64 r; asm("mov.b64 %0, {%1, %2};" : "=l"(r) : "f"(lo), "f"(hi)); return r;
}
__device__ __forceinline__ void upk2(float& lo, float& hi, u64 v) {
    asm("mov.b64 {%0, %1}, %2;" : "=f"(lo), "=f"(hi) : "l"(v));
}
__device__ __forceinline__ void ffma2(u64& d, u64 a, u64 b) {
    asm("fma.rn.f32x2 %0, %1, %2, %0;" : "+l"(d) : "l"(a), "l"(b));
}

// ---- cp.async helpers -----------------------------------------------------
__device__ __forceinline__ void cpa4(uint32_t d, const void* s) {
    asm volatile("cp.async.ca.shared.global [%0], [%1], 4;" :: "r"(d), "l"(s) : "memory");
}
#define CP_COMMIT() asm volatile("cp.async.commit_group;" ::: "memory")
#define CP_WAIT0()  asm volatile("cp.async.wait_group 0;" ::: "memory")
#define CP_WAIT1()  asm volatile("cp.async.wait_group 1;" ::: "memory")

// ---------------------------------------------------------------------------
// Degree / normalization
// ---------------------------------------------------------------------------
__global__ void k_init_deg() {
    int i = blockIdx.x * blockDim.x + threadIdx.x;
    if (i < NN) g_dinv[i] = 1.0f;     // self-loop contributes 1 to every degree
}

__global__ __launch_bounds__(256) void k_count_deg(const int* __restrict__ col) {
    for (int e = blockIdx.x * blockDim.x + threadIdx.x; e < NE;
         e += gridDim.x * blockDim.x)
        atomicAdd(&g_dinv[col[e]], 1.0f);
}

__global__ void k_finalize_dinv() {
    int i = blockIdx.x * blockDim.x + threadIdx.x;
    if (i < NN) g_dinv[i] = rsqrtf(g_dinv[i]);   // deg >= 1 always
}

// ---------------------------------------------------------------------------
// GEMM1: hs[n][k] = (sum_h x[n][h] * Wd[k][h]) * dinv[n]
//        agg[n][k] = hs[n][k] * dinv[n]          (self-loop init)
// 256 rows/block, 128 threads, 8x8 thread tile (row-pairs packed in f32x2).
// A transposed in smem [hh][r] -> dense LDS.64 pair loads (2 wf).
// B pre-duplicated u64 [hh][k]  -> warp-uniform broadcast loads (1 wf).
// cp.async double buffer for A; register->STS pipeline for tiny B chunk.
// ---------------------------------------------------------------------------
#define GD_CH 16                      // hh per chunk
__global__ __launch_bounds__(128) void k_gemm_down(const float* __restrict__ x,
                                                   const float* __restrict__ Wd) {
    __shared__ __align__(16) float As[2][GD_CH * 260];  // [hh][r], pad 260  (33,280 B)
    __shared__ __align__(16) u64  Bsd[2][GD_CH * 32];   // dup w   [hh][k]   ( 8,192 B)

    int tid = threadIdx.x;
    int lane = tid & 31;              // row-pair index
    int wid = tid >> 5;               // 4 warps -> col group 8*wid
    int rowbase = blockIdx.x * 256;

    uint32_t as0 = (uint32_t)__cvta_generic_to_shared(&As[0][0]);

    // async-stage A chunk (transposed, scalar cp.async)
    auto stageA = [&](int ch, int buf) {
        uint32_t dst = as0 + buf * (GD_CH * 260 * 4);
        int hbase = ch * GD_CH;
#pragma unroll
        for (int q = 0; q < 32; q++) {
            int id = tid + q * 128;   // 0..4095
            int hh = id & 15;
            int r = id >> 4;          // 0..255
            int gr = rowbase + r; if (gr >= NN) gr = NN - 1;
            cpa4(dst + (hh * 260 + r) * 4, &x[gr * HID + hbase + hh]);
        }
    };
    // sync-prefetch B chunk into 4 regs (coalesced 64B rows)
    float wb[4];
    auto fetchB = [&](int ch) {
        int hbase = ch * GD_CH;
#pragma unroll
        for (int q = 0; q < 4; q++) {
            int id = tid + q * 128;   // 0..511
            int hh = id & 15;
            int k = id >> 4;          // 0..31
            wb[q] = Wd[k * HID + hbase + hh];
        }
    };

    u64 acc[32];                      // [j(4 row-pairs)][c(8 cols)]
#pragma unroll
    for (int i = 0; i < 32; i++) acc[i] = 0ULL;

    fetchB(0);
    stageA(0, 0); CP_COMMIT();

    for (int ch = 0; ch < HID / GD_CH; ch++) {
        int buf = ch & 1;
        bool more = (ch + 1 < HID / GD_CH);
        if (more) { stageA(ch + 1, buf ^ 1); CP_COMMIT(); }

        // commit current B (dup) to smem; prev compute's trailing sync protects buffer
        {
#pragma unroll
            for (int q = 0; q < 4; q++) {
                int id = tid + q * 128;
                int hh = id & 15;
                int k = id >> 4;
                Bsd[buf][hh * 32 + k] = pk2(wb[q], wb[q]);
            }
        }
        if (more) fetchB(ch + 1);     // overlaps with compute below

        if (more) CP_WAIT1(); else CP_WAIT0();
        __syncthreads();

        const float* A = &As[buf][0];
        const u64*  W = &Bsd[buf][0];
#pragma unroll
        for (int hh = 0; hh < GD_CH; hh++) {
            u64 w[8];
#pragma unroll
            for (int c = 0; c < 8; c++) w[c] = W[hh * 32 + 8 * wid + c];
            u64 a2[4];
#pragma unroll
            for (int j = 0; j < 4; j++)
                a2[j] = *(const u64*)&A[hh * 260 + 2 * lane + 64 * j];
#pragma unroll
            for (int j = 0; j < 4; j++)
#pragma unroll
                for (int c = 0; c < 8; c++)
                    ffma2(acc[j * 8 + c], a2[j], w[c]);
        }
        __syncthreads();
    }

    // epilogue: rows 2*lane + 64*j (+1), cols 8*wid..+7
#pragma unroll
    for (int j = 0; j < 4; j++) {
        float lo[8], hi[8];
#pragma unroll
        for (int c = 0; c < 8; c++) upk2(lo[c], hi[c], acc[j * 8 + c]);
        int r0 = rowbase + 2 * lane + 64 * j;
#pragma unroll
        for (int half = 0; half < 2; half++) {
            int r = r0 + half;
            if (r < NN) {
                const float* v = half ? hi : lo;
                float di = g_dinv[r];
                float d2 = di * di;
                float4 h0 = make_float4(v[0]*di, v[1]*di, v[2]*di, v[3]*di);
                float4 h1 = make_float4(v[4]*di, v[5]*di, v[6]*di, v[7]*di);
                *(float4*)&g_hs[r * BN + 8 * wid + 0] = h0;
                *(float4*)&g_hs[r * BN + 8 * wid + 4] = h1;
                float4 a0 = make_float4(v[0]*d2, v[1]*d2, v[2]*d2, v[3]*d2);
                float4 a1 = make_float4(v[4]*d2, v[5]*d2, v[6]*d2, v[7]*d2);
                *(float4*)&g_agg[r * BN + 8 * wid + 0] = a0;
                *(float4*)&g_agg[r * BN + 8 * wid + 4] = a1;
            }
        }
    }
}

// ---------------------------------------------------------------------------
// Edge scatter: agg[col] += hs[row] * dinv[col]
// 8 lanes/edge: one float4 gather + one red.global.add.v4.f32 per lane.
// ---------------------------------------------------------------------------
__global__ __launch_bounds__(256) void k_scatter(const int* __restrict__ rows,
                                                 const int* __restrict__ cols) {
    int t = blockIdx.x * 256 + threadIdx.x;
    int e = t >> 3;
    if (e >= NE) return;
    int j = t & 7;
    int r = rows[e];
    int c = cols[e];
    float dc = __ldg(&g_dinv[c]);
    float4 v = __ldg(((const float4*)g_hs) + (r * 8 + j));
    float4* dst = ((float4*)g_agg) + (c * 8 + j);
    asm volatile("red.global.add.v4.f32 [%0], {%1, %2, %3, %4};"
                 :: "l"(dst), "f"(v.x * dc), "f"(v.y * dc), "f"(v.z * dc), "f"(v.w * dc)
                 : "memory");
}

// ---------------------------------------------------------------------------
// ReLU + bias (float4), then pre-scale for conv2 and re-init agg w/ self-loop
// ---------------------------------------------------------------------------
__global__ __launch_bounds__(256) void k_relu_stage(const float* __restrict__ bd) {
    int i4 = blockIdx.x * blockDim.x + threadIdx.x;   // < NN*BN/4
    int n = i4 >> 3;
    float di = g_dinv[n];
    float4 a = ((const float4*)g_agg)[i4];
    float4 b = ((const float4*)bd)[i4 & 7];
    float4 v;
    v.x = fmaxf(a.x + b.x, 0.0f) * di;
    v.y = fmaxf(a.y + b.y, 0.0f) * di;
    v.z = fmaxf(a.z + b.z, 0.0f) * di;
    v.w = fmaxf(a.w + b.w, 0.0f) * di;
    ((float4*)g_hs)[i4] = v;
    float4 ag = make_float4(v.x * di, v.y * di, v.z * di, v.w * di);
    ((float4*)g_agg)[i4] = ag;
}

// ---------------------------------------------------------------------------
// GEMM2 + epilogue: out[n][h] = sum_k agg[n][k] * Wu[h][k] + bu[h] + x[n][h]
// 128 rows/block, 256 threads, 8 rows x 4 cols/thread; row-pairs packed f32x2.
// A transposed [k][r] -> warp-uniform broadcast LDS.64 pair loads.
// W per thread: one LDS.128 (4 cols) + 4 dup MOVs. Coalesced float4 epilogue.
// ---------------------------------------------------------------------------
__global__ __launch_bounds__(256) void k_gemm_up(const float* __restrict__ x,
                                                 const float* __restrict__ Wu,
                                                 const float* __restrict__ bu,
                                                 float* __restrict__ out) {
    __shared__ __align__(16) float Bs2[32 * 260];    // [k][h] = Wu[h][k] (33,280 B)
    __shared__ __align__(16) float As2[2][32 * 34];  // [k][r] transposed ( 8,704 B)

    int tid = threadIdx.x;
    int cx = tid & 63;                // cols 4*cx .. 4*cx+3
    int ry = tid >> 6;                // 0..3 (warp-uniform): rows ry*8 .. +7
    int blockrow = blockIdx.x * 128;

    uint32_t bs2b = (uint32_t)__cvta_generic_to_shared(&Bs2[0]);
    uint32_t as2b = (uint32_t)__cvta_generic_to_shared(&As2[0][0]);

    auto stage_tile = [&](int t, int buf) {
        int rb = blockrow + t * 32;
        uint32_t dst = as2b + buf * (32 * 34 * 4);
#pragma unroll
        for (int q = 0; q < 4; q++) {
            int id = tid + q * 256;   // 0..1023
            int k = id & 31;          // lanes: consecutive k -> coalesced src
            int r = id >> 5;
            int gr = rb + r; if (gr >= NN) gr = NN - 1;
            cpa4(dst + (k * 34 + r) * 4, &g_agg[gr * BN + k]);
        }
    };

    // group 0: weights (transposed) + tile 0
#pragma unroll
    for (int q = 0; q < 32; q++) {
        int idx = tid + q * 256;      // 0..8191 = h*32+k
        int h = idx >> 5;
        int k = idx & 31;
        cpa4(bs2b + (k * 260 + h) * 4, &Wu[idx]);
    }
    stage_tile(0, 0);
    CP_COMMIT();

    float4 b4 = *(const float4*)&bu[4 * cx];

    for (int t = 0; t < 4; t++) {
        int buf = t & 1;
        if (t + 1 < 4) { stage_tile(t + 1, buf ^ 1); CP_COMMIT(); CP_WAIT1(); }
        else           { CP_WAIT0(); }
        __syncthreads();

        u64 acc[16];                  // [p(4 row-pairs)][c(4 cols)]
#pragma unroll
        for (int i = 0; i < 16; i++) acc[i] = 0ULL;

        const float* A = &As2[buf][0];
#pragma unroll 8
        for (int k = 0; k < 32; k++) {
            float4 wv = *(const float4*)&Bs2[k * 260 + 4 * cx];
            u64 wd[4];
            wd[0] = pk2(wv.x, wv.x);
            wd[1] = pk2(wv.y, wv.y);
            wd[2] = pk2(wv.z, wv.z);
            wd[3] = pk2(wv.w, wv.w);
            u64 a2[4];
#pragma unroll
            for (int p = 0; p < 4; p++)
                a2[p] = *(const u64*)&A[k * 34 + ry * 8 + 2 * p];
#pragma unroll
            for (int p = 0; p < 4; p++)
#pragma unroll
                for (int c = 0; c < 4; c++)
                    ffma2(acc[p * 4 + c], a2[p], wd[c]);
        }

        int rb = blockrow + t * 32;
#pragma unroll
        for (int p = 0; p < 4; p++) {
            float lo[4], hi[4];
#pragma unroll
            for (int c = 0; c < 4; c++) upk2(lo[c], hi[c], acc[p * 4 + c]);
            int r0 = rb + ry * 8 + 2 * p;
#pragma unroll
            for (int half = 0; half < 2; half++) {
                int r = r0 + half;
                if (r < NN) {
                    const float* v = half ? hi : lo;
                    float4 xv = *(const float4*)&x[r * HID + 4 * cx];
                    float4 o;
                    o.x = v[0] + b4.x + xv.x;
                    o.y = v[1] + b4.y + xv.y;
                    o.z = v[2] + b4.z + xv.z;
                    o.w = v[3] + b4.w + xv.w;
                    *(float4*)&out[r * HID + 4 * cx] = o;
                }
            }
        }
        __syncthreads();
    }
}

// ---------------------------------------------------------------------------
extern "C" void kernel_launch(void* const* d_in, const int* in_sizes, int n_in,
                              void* d_out, int out_size) {
    // Resolve inputs by element count (robust to metadata ordering).
    // edge_index is int32 (JAX x64 disabled -> int64 request yields int32).
    const float* x = 0; const int* ei = 0;
    const float* Wd = 0; const float* bd = 0;
    const float* Wu = 0; const float* bu = 0;
    for (int i = 0; i < n_in; i++) {
        int sz = in_sizes[i];
        if (sz == NN * HID)       x  = (const float*)d_in[i];
        else if (sz == 2 * NE)    ei = (const int*)d_in[i];
        else if (sz == BN * HID) { if (!Wd) Wd = (const float*)d_in[i];
                                   else     Wu = (const float*)d_in[i]; }
        else if (sz == BN)        bd = (const float*)d_in[i];
        else if (sz == HID)       bu = (const float*)d_in[i];
    }
    float* out = (float*)d_out;

    const int* erow = ei;        // edge_index[0] = source
    const int* ecol = ei + NE;   // edge_index[1] = target

    k_init_deg<<<(NN + 255) / 256, 256>>>();
    k_count_deg<<<592, 256>>>(ecol);
    k_finalize_dinv<<<(NN + 255) / 256, 256>>>();

    k_gemm_down<<<(NN + 255) / 256, 128>>>(x, Wd);
    k_scatter<<<(NE * 8) / 256, 256>>>(erow, ecol);
    k_relu_stage<<<(NN * BN / 4 + 255) / 256, 256>>>(bd);
    k_scatter<<<(NE * 8) / 256, 256>>>(erow, ecol);
    k_gemm_up<<<(NN + 127) / 128, 256>>>(x, Wu, bu, out);
}